// round 2
// baseline (speedup 1.0000x reference)
#include <cuda_runtime.h>
#include <math.h>

#define SEQ   512
#define BATCH 64
#define DIM   512
#define G4    2048
#define NT    8
#define HD    64
#define TL    64
#define NACT  72
#define MROWS (SEQ*BATCH)

__device__ float g_xg [(size_t)MROWS*G4];
__device__ float g_val[(size_t)MROWS*DIM];
__device__ float g_hT [(size_t)(SEQ+1)*DIM*BATCH];
__device__ float g_act[(size_t)MROWS*NACT];
__device__ float g_ro [(size_t)MROWS*DIM];
__device__ unsigned g_bar;

__device__ __forceinline__ float sigf(float x){ return 1.f/(1.f+__expf(-x)); }

__global__ void init_kernel(){
  unsigned i = blockIdx.x*256u + threadIdx.x;
  if (i==0) g_bar = 0u;
  if (i < DIM*BATCH) g_hT[i] = 0.f;
}

// C[m][n] = sum_k A[m][k]*W[n][k] + b1[n] (+ b2[n]); tile 128x128, BK=16
__launch_bounds__(256)
__global__ void sgemm_bias(const float* __restrict__ A, const float* __restrict__ W,
                           const float* __restrict__ b1, const float* __restrict__ b2,
                           float* __restrict__ C, int N, int K)
{
  __shared__ float As[16][128];
  __shared__ float Ws[16][128];
  const int t = threadIdx.x, tr = t>>4, tc = t&15;
  float acc[8][8];
#pragma unroll
  for (int i=0;i<8;i++)
#pragma unroll
    for (int j=0;j<8;j++) acc[i][j]=0.f;

  const float* Ab = A + (size_t)blockIdx.y*128*K;
  const float* Wb = W + (size_t)blockIdx.x*128*K;

  for (int k0=0;k0<K;k0+=16){
#pragma unroll
    for (int i=0;i<2;i++){
      int id = t + i*256, row = id>>2, kk = (id&3)<<2;
      float4 av = *(const float4*)(Ab + (size_t)row*K + k0 + kk);
      As[kk+0][row]=av.x; As[kk+1][row]=av.y; As[kk+2][row]=av.z; As[kk+3][row]=av.w;
      float4 wv = *(const float4*)(Wb + (size_t)row*K + k0 + kk);
      Ws[kk+0][row]=wv.x; Ws[kk+1][row]=wv.y; Ws[kk+2][row]=wv.z; Ws[kk+3][row]=wv.w;
    }
    __syncthreads();
#pragma unroll
    for (int k=0;k<16;k++){
      float ar[8], wr[8];
      *(float4*)(ar)   = *(const float4*)&As[k][tr*4];
      *(float4*)(ar+4) = *(const float4*)&As[k][64+tr*4];
      *(float4*)(wr)   = *(const float4*)&Ws[k][tc*4];
      *(float4*)(wr+4) = *(const float4*)&Ws[k][64+tc*4];
#pragma unroll
      for (int i=0;i<8;i++)
#pragma unroll
        for (int j=0;j<8;j++) acc[i][j] += ar[i]*wr[j];
    }
    __syncthreads();
  }
  const int r0 = blockIdx.y*128, c0 = blockIdx.x*128;
#pragma unroll
  for (int i=0;i<8;i++){
    int r = r0 + ((i<4) ? (tr*4+i) : (64+tr*4+i-4));
#pragma unroll
    for (int jv=0;jv<2;jv++){
      int cc = c0 + (jv ? (64+tc*4) : (tc*4));
      float4 o;
      o.x = acc[i][jv*4+0]+b1[cc+0]+(b2?b2[cc+0]:0.f);
      o.y = acc[i][jv*4+1]+b1[cc+1]+(b2?b2[cc+1]:0.f);
      o.z = acc[i][jv*4+2]+b1[cc+2]+(b2?b2[cc+2]:0.f);
      o.w = acc[i][jv*4+3]+b1[cc+3]+(b2?b2[cc+3]:0.f);
      *(float4*)(C + (size_t)r*N + cc) = o;
    }
  }
}

// persistent LSTM: 128 CTAs x 256 thr; CTA owns hidden cols [c0,c0+4)
__launch_bounds__(256)
__global__ void lstm_kernel(const float* __restrict__ W_hh)
{
  __shared__ float4 Ws4[128*16];
  __shared__ float  gs[16*68];
  const int t = threadIdx.x, c0 = blockIdx.x*4;

  for (int i=t;i<2048;i+=256){
    int col16 = i&15, k4 = i>>4;
    int r = (col16>>2)*DIM + c0 + (col16&3);
    Ws4[i] = *(const float4*)(W_hh + (size_t)r*DIM + k4*4);
  }
  const int col16 = t>>4;
  const int b0 = (t&15)*4;
  const int xg_row = (col16>>2)*DIM + c0 + (col16&3);
  const int b2 = t&63, j2 = t>>6;
  float cstate = 0.f;
  __syncthreads();

  for (int s=0;s<SEQ;s++){
    const float* __restrict__ hprev = g_hT + (size_t)s*DIM*BATCH;
    const float* __restrict__ xgp = g_xg + ((size_t)s*BATCH + b0)*G4 + xg_row;
    float a0 = xgp[0], a1 = xgp[G4], a2 = xgp[2*(size_t)G4], a3 = xgp[3*(size_t)G4];
#pragma unroll 4
    for (int k4=0;k4<128;k4++){
      float4 w = Ws4[k4*16 + col16];
      const float* hp = hprev + k4*4*BATCH + b0;
      float4 h0 = *(const float4*)(hp);
      float4 h1 = *(const float4*)(hp + BATCH);
      float4 h2 = *(const float4*)(hp + 2*BATCH);
      float4 h3 = *(const float4*)(hp + 3*BATCH);
      a0 += w.x*h0.x + w.y*h1.x + w.z*h2.x + w.w*h3.x;
      a1 += w.x*h0.y + w.y*h1.y + w.z*h2.y + w.w*h3.y;
      a2 += w.x*h0.z + w.y*h1.z + w.z*h2.z + w.w*h3.z;
      a3 += w.x*h0.w + w.y*h1.w + w.z*h2.w + w.w*h3.w;
    }
    *(float4*)&gs[col16*68 + b0] = make_float4(a0,a1,a2,a3);
    __syncthreads();
    {
      float gi = gs[( 0+j2)*68 + b2];
      float gf = gs[( 4+j2)*68 + b2];
      float gg = gs[( 8+j2)*68 + b2];
      float go = gs[(12+j2)*68 + b2];
      cstate = sigf(gf)*cstate + sigf(gi)*tanhf(gg);
      g_hT[((size_t)(s+1)*DIM + (c0+j2))*BATCH + b2] = sigf(go)*tanhf(cstate);
    }
    __syncthreads();
    if (t==0){
      __threadfence();
      atomicAdd(&g_bar, 1u);
      unsigned target = (unsigned)(s+1)*128u;
      while (*(volatile unsigned*)&g_bar < target) { }
    }
    __syncthreads();
  }
}

// actions[s][b][a] = h[s] @ W_act.T + b_act  (N=72)
__launch_bounds__(256)
__global__ void actions_kernel(const float* __restrict__ W_act, const float* __restrict__ b_act)
{
  __shared__ float hs[64*64];
  __shared__ float ws[NACT*64];
  const int s = blockIdx.x, t = threadIdx.x;
  const int b = t&63, ag = t>>6;
  const float* hT = g_hT + (size_t)(s+1)*DIM*BATCH;
  float acc[18];
#pragma unroll
  for (int i=0;i<18;i++) acc[i]=0.f;

  for (int j0=0;j0<DIM;j0+=64){
#pragma unroll
    for (int i=0;i<4;i++){
      int id = t + i*256;
      ((float4*)hs)[id] = ((const float4*)(hT + (size_t)j0*BATCH))[id];
    }
    for (int i=t;i<NACT*16;i+=256){
      int a = i>>4, jj = i&15;
      *(float4*)&ws[a*64 + jj*4] = *(const float4*)(W_act + (size_t)a*DIM + j0 + jj*4);
    }
    __syncthreads();
#pragma unroll 8
    for (int j=0;j<64;j++){
      float hv = hs[j*64 + b];
#pragma unroll
      for (int ii=0;ii<18;ii++) acc[ii] += hv * ws[(ag*18+ii)*64 + j];
    }
    __syncthreads();
  }
#pragma unroll
  for (int ii=0;ii<18;ii++){
    int a = ag*18+ii;
    g_act[((size_t)s*BATCH + b)*NACT + a] = acc[ii] + b_act[a];
  }
}

// NTM scan: 1 CTA per (batch,tape); thread c owns tape[:,c] in regs
__launch_bounds__(64)
__global__ void tape_kernel(float* __restrict__ out)
{
  __shared__ float wpos[TL], rpos[TL], rpr[TL];
  const int bb = blockIdx.x>>3, tp = blockIdx.x&7, c = threadIdx.x;
  float tape[TL];
#pragma unroll
  for (int l=0;l<TL;l++) tape[l]=0.f;
  wpos[c] = (c==0)?1.f:0.f;
  rpos[c] = (c==0)?1.f:0.f;
  __syncthreads();

  for (int s=0;s<SEQ;s++){
    const float* ap = g_act + ((size_t)s*BATCH + bb)*NACT + tp*9;
    float r0=ap[0], r1=ap[1], r2=ap[2];
    float w0=ap[3], w1=ap[4], w2=ap[5];
    float rw0=sigf(ap[6]), rw1=sigf(ap[7]), rw2=sigf(ap[8]);

    float mr = fmaxf(r0,fmaxf(r1,r2));
    float e0=__expf(r0-mr), e1=__expf(r1-mr), e2=__expf(r2-mr);
    float ir = 1.f/(e0+e1+e2);
    float rd0=e0*ir, rd1=e1*ir, rd2=e2*ir;
    float mw = fmaxf(w0,fmaxf(w1,w2));
    float f0=__expf(w0-mw), f1=__expf(w1-mw), f2=__expf(w2-mw);
    float iw = 1.f/(f0+f1+f2);
    float wd0=f0*iw, wd1=f1*iw, wd2=f2*iw;

    float v = g_val[((size_t)s*BATCH + bb)*DIM + tp*HD + c];

    float oldv = 0.f;
#pragma unroll
    for (int l=0;l<TL;l++) oldv += tape[l]*wpos[l];

    float nw = wpos[(c+1)&63]*wd0 + wpos[c]*wd1 + wpos[(c+63)&63]*wd2;
    float nr = rpos[(c+1)&63]*rd0 + rpos[c]*rd1 + rpos[(c+63)&63]*rd2;
    rpr[c] = rpos[c]*rw0;
    __syncthreads();

    float upd = v*rw1 - oldv*rw2;
    float ro = 0.f;
#pragma unroll
    for (int l=0;l<TL;l++){
      tape[l] += wpos[l]*upd;
      ro += tape[l]*rpr[l];
    }
    __syncthreads();
    wpos[c]=nw; rpos[c]=nr;
    g_ro[((size_t)s*BATCH + bb)*DIM + tp*HD + c] = ro;
    __syncthreads();
  }
#pragma unroll
  for (int l=0;l<TL;l++)
    out[(size_t)SEQ*BATCH*DIM + ((size_t)l*BATCH + bb)*DIM + tp*HD + c] = tape[l];
}

extern "C" void kernel_launch(void* const* d_in, const int* in_sizes, int n_in,
                              void* d_out, int out_size)
{
  const float* inputs = (const float*)d_in[0];
  const float* W_ih   = (const float*)d_in[1];
  const float* W_hh   = (const float*)d_in[2];
  const float* b_ih   = (const float*)d_in[3];
  const float* b_hh   = (const float*)d_in[4];
  const float* W_act  = (const float*)d_in[5];
  const float* b_act  = (const float*)d_in[6];
  const float* W_val  = (const float*)d_in[7];
  const float* b_val  = (const float*)d_in[8];
  const float* W_out  = (const float*)d_in[9];
  const float* b_out  = (const float*)d_in[10];
  float* out = (float*)d_out;

  float *xg_p, *val_p, *ro_p;
  cudaGetSymbolAddress((void**)&xg_p,  g_xg);
  cudaGetSymbolAddress((void**)&val_p, g_val);
  cudaGetSymbolAddress((void**)&ro_p,  g_ro);

  init_kernel<<<128,256>>>();
  sgemm_bias<<<dim3(16,256),256>>>(inputs, W_ih, b_ih, b_hh, xg_p, G4, DIM);
  sgemm_bias<<<dim3(4,256),256>>>(inputs, W_val, b_val, nullptr, val_p, DIM, DIM);
  lstm_kernel<<<128,256>>>(W_hh);
  actions_kernel<<<SEQ,256>>>(W_act, b_act);
  tape_kernel<<<512,64>>>(out);
  sgemm_bias<<<dim3(4,256),256>>>(ro_p, W_out, b_out, nullptr, out, DIM, DIM);
}

// round 3
// speedup vs baseline: 2.7106x; 2.7106x over previous
#include <cuda_runtime.h>
#include <math.h>

#define SEQ   512
#define BATCH 64
#define DIM   512
#define G4    2048
#define NT    8
#define HD    64
#define TL    64
#define NACT  72
#define MROWS (SEQ*BATCH)

__device__ float g_xg [(size_t)MROWS*G4];
__device__ float g_val[(size_t)MROWS*DIM];
__device__ float g_hT [(size_t)(SEQ+1)*DIM*BATCH];
__device__ float g_act[(size_t)MROWS*NACT];
__device__ float g_ro [(size_t)MROWS*DIM];
__device__ unsigned g_bar;

__device__ __forceinline__ float sigf(float x){ return 1.f/(1.f+__expf(-x)); }

__device__ __forceinline__ void cp16(void* dst_smem, const void* src){
  unsigned d = (unsigned)__cvta_generic_to_shared(dst_smem);
  asm volatile("cp.async.ca.shared.global [%0], [%1], 16;\n" :: "r"(d), "l"(src));
}
#define CP_COMMIT() asm volatile("cp.async.commit_group;\n" ::: "memory")
#define CP_WAIT1()  asm volatile("cp.async.wait_group 1;\n" ::: "memory")

__global__ void init_kernel(){
  unsigned i = blockIdx.x*256u + threadIdx.x;
  if (i==0) g_bar = 0u;
  if (i < DIM*BATCH) g_hT[i] = 0.f;
}

// C[m][n] = sum_k A[m][k]*W[n][k] + b1[n] (+ b2[n]); tile 128x128, BK=16
__launch_bounds__(256)
__global__ void sgemm_bias(const float* __restrict__ A, const float* __restrict__ W,
                           const float* __restrict__ b1, const float* __restrict__ b2,
                           float* __restrict__ C, int N, int K)
{
  __shared__ float As[16][128];
  __shared__ float Ws[16][128];
  const int t = threadIdx.x, tr = t>>4, tc = t&15;
  float acc[8][8];
#pragma unroll
  for (int i=0;i<8;i++)
#pragma unroll
    for (int j=0;j<8;j++) acc[i][j]=0.f;

  const float* Ab = A + (size_t)blockIdx.y*128*K;
  const float* Wb = W + (size_t)blockIdx.x*128*K;

  for (int k0=0;k0<K;k0+=16){
#pragma unroll
    for (int i=0;i<2;i++){
      int id = t + i*256, row = id>>2, kk = (id&3)<<2;
      float4 av = *(const float4*)(Ab + (size_t)row*K + k0 + kk);
      As[kk+0][row]=av.x; As[kk+1][row]=av.y; As[kk+2][row]=av.z; As[kk+3][row]=av.w;
      float4 wv = *(const float4*)(Wb + (size_t)row*K + k0 + kk);
      Ws[kk+0][row]=wv.x; Ws[kk+1][row]=wv.y; Ws[kk+2][row]=wv.z; Ws[kk+3][row]=wv.w;
    }
    __syncthreads();
#pragma unroll
    for (int k=0;k<16;k++){
      float ar[8], wr[8];
      *(float4*)(ar)   = *(const float4*)&As[k][tr*4];
      *(float4*)(ar+4) = *(const float4*)&As[k][64+tr*4];
      *(float4*)(wr)   = *(const float4*)&Ws[k][tc*4];
      *(float4*)(wr+4) = *(const float4*)&Ws[k][64+tc*4];
#pragma unroll
      for (int i=0;i<8;i++)
#pragma unroll
        for (int j=0;j<8;j++) acc[i][j] += ar[i]*wr[j];
    }
    __syncthreads();
  }
  const int r0 = blockIdx.y*128, c0 = blockIdx.x*128;
#pragma unroll
  for (int i=0;i<8;i++){
    int r = r0 + ((i<4) ? (tr*4+i) : (64+tr*4+i-4));
#pragma unroll
    for (int jv=0;jv<2;jv++){
      int cc = c0 + (jv ? (64+tc*4) : (tc*4));
      float4 o;
      o.x = acc[i][jv*4+0]+b1[cc+0]+(b2?b2[cc+0]:0.f);
      o.y = acc[i][jv*4+1]+b1[cc+1]+(b2?b2[cc+1]:0.f);
      o.z = acc[i][jv*4+2]+b1[cc+2]+(b2?b2[cc+2]:0.f);
      o.w = acc[i][jv*4+3]+b1[cc+3]+(b2?b2[cc+3]:0.f);
      *(float4*)(C + (size_t)r*N + cc) = o;
    }
  }
}

// ---------- LSTM v2: SMEM-staged h, 4x4 register tiles, 4-way split-K -------
// 128 CTAs x 256 thr. CTA owns 4 hidden cols (16 gate rows) x 64 batches.
// thread: kw=t>>6 (k-way), g=(t>>4)&3 (gate), bq=t&15 (batch quad)
// dyn smem: Ws[512][16] 32KB | hs[2][128][64] 64KB | red[4][16][64] 16KB
#define LS_SMEM (114688)
extern __shared__ float ls_smem[];

__launch_bounds__(256)
__global__ void lstm2_kernel(const float* __restrict__ W_hh)
{
  float* Ws  = ls_smem;           // [k][row16]
  float* hs0 = ls_smem + 8192;    // [128][64]
  float* hs1 = ls_smem + 16384;
  float* red = ls_smem + 24576;   // [kw][row16][b]

  const int t  = threadIdx.x;
  const int c0 = blockIdx.x*4;
  const int kw = t>>6;
  const int g  = (t>>4)&3;
  const int bq = t&15;
  const int fj = t>>6, fb = t&63;   // final role: hidden col j, batch b

  for (int id = t; id < 8192; id += 256){
    int row16 = id >> 9, k = id & 511;
    int gg = row16 >> 2, jj = row16 & 3;
    Ws[k*16 + row16] = W_hh[(size_t)(gg*DIM + c0 + jj)*DIM + k];
  }
  float cstate = 0.f;
  __syncthreads();

  for (int s = 0; s < SEQ; s++){
    const float* hbase = g_hT + (size_t)s*DIM*BATCH;   // [k][b]
    // prefetch xg (consumed ~6000 cyc later)
    const float* xgp = g_xg + ((size_t)s*BATCH + fb)*G4 + c0 + fj;
    float x0 = xgp[0], x1 = xgp[DIM], x2 = xgp[2*DIM], x3 = xgp[3*DIM];

    // prefetch chunks 0,1
#pragma unroll
    for (int i=0;i<8;i++){ int id = t + i*256; int row = id>>4, col = id&15;
      cp16(hs0 + row*64 + col*4, hbase + (size_t)row*64 + col*4); }
    CP_COMMIT();
#pragma unroll
    for (int i=0;i<8;i++){ int id = t + i*256; int row = id>>4, col = id&15;
      cp16(hs1 + row*64 + col*4, hbase + (size_t)(128+row)*64 + col*4); }
    CP_COMMIT();

    float acc[4][4];
#pragma unroll
    for (int a=0;a<4;a++)
#pragma unroll
      for (int b=0;b<4;b++) acc[a][b]=0.f;

#pragma unroll
    for (int sc = 0; sc < 4; sc++){
      CP_WAIT1();
      __syncthreads();
      const float* hc = (sc&1) ? hs1 : hs0;
      const float* wp = Ws + ((size_t)(sc*128 + kw*32))*16 + g*4;
      const float* hp = hc + (kw*32)*64 + bq*4;
#pragma unroll 8
      for (int k=0;k<32;k++){
        float4 w = *(const float4*)(wp + k*16);
        float4 h = *(const float4*)(hp + k*64);
        acc[0][0]+=w.x*h.x; acc[0][1]+=w.x*h.y; acc[0][2]+=w.x*h.z; acc[0][3]+=w.x*h.w;
        acc[1][0]+=w.y*h.x; acc[1][1]+=w.y*h.y; acc[1][2]+=w.y*h.z; acc[1][3]+=w.y*h.w;
        acc[2][0]+=w.z*h.x; acc[2][1]+=w.z*h.y; acc[2][2]+=w.z*h.z; acc[2][3]+=w.z*h.w;
        acc[3][0]+=w.w*h.x; acc[3][1]+=w.w*h.y; acc[3][2]+=w.w*h.z; acc[3][3]+=w.w*h.w;
      }
      __syncthreads();    // everyone done reading this buffer
      if (sc < 2){
        float* dst = (sc&1) ? hs1 : hs0;
#pragma unroll
        for (int i=0;i<8;i++){ int id = t + i*256; int row = id>>4, col = id&15;
          cp16(dst + row*64 + col*4, hbase + (size_t)((sc+2)*128+row)*64 + col*4); }
      }
      CP_COMMIT();   // empty groups for sc>=2 keep wait_group bookkeeping aligned
    }

    // split-K reduction
#pragma unroll
    for (int a=0;a<4;a++)
      *(float4*)&red[(size_t)(kw*16 + g*4 + a)*64 + bq*4] =
          make_float4(acc[a][0],acc[a][1],acc[a][2],acc[a][3]);
    __syncthreads();

    float gi = x0, gf = x1, gg2 = x2, go = x3;
#pragma unroll
    for (int k2=0;k2<4;k2++){
      gi  += red[(k2*16 +  0 + fj)*64 + fb];
      gf  += red[(k2*16 +  4 + fj)*64 + fb];
      gg2 += red[(k2*16 +  8 + fj)*64 + fb];
      go  += red[(k2*16 + 12 + fj)*64 + fb];
    }
    cstate = sigf(gf)*cstate + sigf(gi)*tanhf(gg2);
    g_hT[((size_t)(s+1)*DIM + (c0+fj))*BATCH + fb] = sigf(go)*tanhf(cstate);

    __syncthreads();
    if (t==0){
      __threadfence();
      atomicAdd(&g_bar, 1u);
      unsigned target = (unsigned)(s+1)*128u;
      while (*(volatile unsigned*)&g_bar < target) { }
    }
    __syncthreads();
  }
}

// actions[s][b][a] = h[s] @ W_act.T + b_act  (N=72)
__launch_bounds__(256)
__global__ void actions_kernel(const float* __restrict__ W_act, const float* __restrict__ b_act)
{
  __shared__ float hs[64*64];
  __shared__ float ws[NACT*64];
  const int s = blockIdx.x, t = threadIdx.x;
  const int b = t&63, ag = t>>6;
  const float* hT = g_hT + (size_t)(s+1)*DIM*BATCH;
  float acc[18];
#pragma unroll
  for (int i=0;i<18;i++) acc[i]=0.f;

  for (int j0=0;j0<DIM;j0+=64){
#pragma unroll
    for (int i=0;i<4;i++){
      int id = t + i*256;
      ((float4*)hs)[id] = ((const float4*)(hT + (size_t)j0*BATCH))[id];
    }
    for (int i=t;i<NACT*16;i+=256){
      int a = i>>4, jj = i&15;
      *(float4*)&ws[a*64 + jj*4] = *(const float4*)(W_act + (size_t)a*DIM + j0 + jj*4);
    }
    __syncthreads();
#pragma unroll 8
    for (int j=0;j<64;j++){
      float hv = hs[j*64 + b];
#pragma unroll
      for (int ii=0;ii<18;ii++) acc[ii] += hv * ws[(ag*18+ii)*64 + j];
    }
    __syncthreads();
  }
#pragma unroll
  for (int ii=0;ii<18;ii++){
    int a = ag*18+ii;
    g_act[((size_t)s*BATCH + b)*NACT + a] = acc[ii] + b_act[a];
  }
}

// NTM scan: 1 CTA per (batch,tape); thread c owns tape[:,c] in regs
__launch_bounds__(64)
__global__ void tape_kernel(float* __restrict__ out)
{
  __shared__ float wpos[TL], rpos[TL], rpr[TL];
  const int bb = blockIdx.x>>3, tp = blockIdx.x&7, c = threadIdx.x;
  float tape[TL];
#pragma unroll
  for (int l=0;l<TL;l++) tape[l]=0.f;
  wpos[c] = (c==0)?1.f:0.f;
  rpos[c] = (c==0)?1.f:0.f;
  __syncthreads();

  for (int s=0;s<SEQ;s++){
    const float* ap = g_act + ((size_t)s*BATCH + bb)*NACT + tp*9;
    float r0=ap[0], r1=ap[1], r2=ap[2];
    float w0=ap[3], w1=ap[4], w2=ap[5];
    float rw0=sigf(ap[6]), rw1=sigf(ap[7]), rw2=sigf(ap[8]);

    float mr = fmaxf(r0,fmaxf(r1,r2));
    float e0=__expf(r0-mr), e1=__expf(r1-mr), e2=__expf(r2-mr);
    float ir = 1.f/(e0+e1+e2);
    float rd0=e0*ir, rd1=e1*ir, rd2=e2*ir;
    float mw = fmaxf(w0,fmaxf(w1,w2));
    float f0=__expf(w0-mw), f1=__expf(w1-mw), f2=__expf(w2-mw);
    float iw = 1.f/(f0+f1+f2);
    float wd0=f0*iw, wd1=f1*iw, wd2=f2*iw;

    float v = g_val[((size_t)s*BATCH + bb)*DIM + tp*HD + c];

    float oldv = 0.f;
#pragma unroll
    for (int l=0;l<TL;l++) oldv += tape[l]*wpos[l];

    float nw = wpos[(c+1)&63]*wd0 + wpos[c]*wd1 + wpos[(c+63)&63]*wd2;
    float nr = rpos[(c+1)&63]*rd0 + rpos[c]*rd1 + rpos[(c+63)&63]*rd2;
    rpr[c] = rpos[c]*rw0;
    __syncthreads();

    float upd = v*rw1 - oldv*rw2;
    float ro = 0.f;
#pragma unroll
    for (int l=0;l<TL;l++){
      tape[l] += wpos[l]*upd;
      ro += tape[l]*rpr[l];
    }
    __syncthreads();
    wpos[c]=nw; rpos[c]=nr;
    g_ro[((size_t)s*BATCH + bb)*DIM + tp*HD + c] = ro;
    __syncthreads();
  }
#pragma unroll
  for (int l=0;l<TL;l++)
    out[(size_t)SEQ*BATCH*DIM + ((size_t)l*BATCH + bb)*DIM + tp*HD + c] = tape[l];
}

extern "C" void kernel_launch(void* const* d_in, const int* in_sizes, int n_in,
                              void* d_out, int out_size)
{
  const float* inputs = (const float*)d_in[0];
  const float* W_ih   = (const float*)d_in[1];
  const float* W_hh   = (const float*)d_in[2];
  const float* b_ih   = (const float*)d_in[3];
  const float* b_hh   = (const float*)d_in[4];
  const float* W_act  = (const float*)d_in[5];
  const float* b_act  = (const float*)d_in[6];
  const float* W_val  = (const float*)d_in[7];
  const float* b_val  = (const float*)d_in[8];
  const float* W_out  = (const float*)d_in[9];
  const float* b_out  = (const float*)d_in[10];
  float* out = (float*)d_out;

  float *xg_p, *val_p, *ro_p;
  cudaGetSymbolAddress((void**)&xg_p,  g_xg);
  cudaGetSymbolAddress((void**)&val_p, g_val);
  cudaGetSymbolAddress((void**)&ro_p,  g_ro);

  cudaFuncSetAttribute(lstm2_kernel, cudaFuncAttributeMaxDynamicSharedMemorySize, LS_SMEM);

  init_kernel<<<128,256>>>();
  sgemm_bias<<<dim3(16,256),256>>>(inputs, W_ih, b_ih, b_hh, xg_p, G4, DIM);
  sgemm_bias<<<dim3(4,256),256>>>(inputs, W_val, b_val, nullptr, val_p, DIM, DIM);
  lstm2_kernel<<<128,256,LS_SMEM>>>(W_hh);
  actions_kernel<<<SEQ,256>>>(W_act, b_act);
  tape_kernel<<<512,64>>>(out);
  sgemm_bias<<<dim3(4,256),256>>>(ro_p, W_out, b_out, nullptr, out, DIM, DIM);
}

// round 4
// speedup vs baseline: 3.1453x; 1.1604x over previous
#include <cuda_runtime.h>
#include <cuda_bf16.h>
#include <math.h>

#define SEQ   512
#define BATCH 64
#define DIM   512
#define G4    2048
#define NT    8
#define HD    64
#define TL    64
#define NACT  72
#define MROWS (SEQ*BATCH)

__device__ float g_xg [(size_t)MROWS*G4];
__device__ float g_val[(size_t)MROWS*DIM];
__device__ float g_hT [(size_t)(SEQ+1)*DIM*BATCH];
__device__ float g_act[(size_t)MROWS*NACT];
__device__ float g_ro [(size_t)MROWS*DIM];
__device__ unsigned g_bar;

__device__ __forceinline__ float sigf(float x){ return 1.f/(1.f+__expf(-x)); }

__device__ __forceinline__ void cp16(void* dst_smem, const void* src){
  unsigned d = (unsigned)__cvta_generic_to_shared(dst_smem);
  asm volatile("cp.async.ca.shared.global [%0], [%1], 16;\n" :: "r"(d), "l"(src));
}
#define CP_COMMIT() asm volatile("cp.async.commit_group;\n" ::: "memory")
#define CP_WAIT1()  asm volatile("cp.async.wait_group 1;\n" ::: "memory")

__global__ void init_kernel(){
  unsigned i = blockIdx.x*256u + threadIdx.x;
  if (i==0) g_bar = 0u;
  if (i < DIM*BATCH) g_hT[i] = 0.f;
}

// ================= bf16-split tensor GEMM ===================================
// C[m][n] = sum_k A[m][k]*W[n][k] + b1[n] (+b2[n]), fp32 in/out.
// Split a = hi + lo (bf16); D = Ah*Wh + Ah*Wl + Al*Wh (fp32 accum).
// CTA tile 128x128, BK=16, 8 warps (2x4), warp tile 64x32, mma m16n8k16.
#define GSTRIDE 24

__device__ __forceinline__ void cvt_store(__nv_bfloat16* Hp, __nv_bfloat16* Lp, float4 v){
  __nv_bfloat16 h0=__float2bfloat16(v.x), h1=__float2bfloat16(v.y);
  __nv_bfloat16 h2=__float2bfloat16(v.z), h3=__float2bfloat16(v.w);
  __nv_bfloat16 l0=__float2bfloat16(v.x-__bfloat162float(h0));
  __nv_bfloat16 l1=__float2bfloat16(v.y-__bfloat162float(h1));
  __nv_bfloat16 l2=__float2bfloat16(v.z-__bfloat162float(h2));
  __nv_bfloat16 l3=__float2bfloat16(v.w-__bfloat162float(h3));
  ((__nv_bfloat162*)Hp)[0] = __nv_bfloat162(h0,h1);
  ((__nv_bfloat162*)Hp)[1] = __nv_bfloat162(h2,h3);
  ((__nv_bfloat162*)Lp)[0] = __nv_bfloat162(l0,l1);
  ((__nv_bfloat162*)Lp)[1] = __nv_bfloat162(l2,l3);
}

#define MMA16816(C, A, B) \
  asm volatile("mma.sync.aligned.m16n8k16.row.col.f32.bf16.bf16.f32 " \
    "{%0,%1,%2,%3}, {%4,%5,%6,%7}, {%8,%9}, {%0,%1,%2,%3};" \
    : "+f"((C)[0]),"+f"((C)[1]),"+f"((C)[2]),"+f"((C)[3]) \
    : "r"((A)[0]),"r"((A)[1]),"r"((A)[2]),"r"((A)[3]), "r"((B)[0]),"r"((B)[1]))

#define LDSM4(R, addr) \
  asm volatile("ldmatrix.sync.aligned.m8n8.x4.shared.b16 {%0,%1,%2,%3}, [%4];" \
    : "=r"((R)[0]),"=r"((R)[1]),"=r"((R)[2]),"=r"((R)[3]) : "r"(addr))

#define LDSM2(R, addr) \
  asm volatile("ldmatrix.sync.aligned.m8n8.x2.shared.b16 {%0,%1}, [%2];" \
    : "=r"((R)[0]),"=r"((R)[1]) : "r"(addr))

__launch_bounds__(256)
__global__ void tgemm_bias(const float* __restrict__ A, const float* __restrict__ W,
                           const float* __restrict__ b1, const float* __restrict__ b2,
                           float* __restrict__ C, int N, int K)
{
  __shared__ __nv_bfloat16 sm[2][4][128*GSTRIDE];  // [buf][Ah,Al,Wh,Wl][row*24+k]
  const int tid = threadIdx.x;
  const int lane = tid & 31, warp = tid >> 5;
  const int warpM = (warp>>2)*64, warpN = (warp&3)*32;
  const int ctaM = blockIdx.y*128, ctaN = blockIdx.x*128;

  float acc[4][4][4];
#pragma unroll
  for (int mf=0;mf<4;mf++)
#pragma unroll
    for (int nf=0;nf<4;nf++)
#pragma unroll
      for (int i=0;i<4;i++) acc[mf][nf][i]=0.f;

  const float* Abase = A + (size_t)ctaM*K;
  const float* Wbase = W + (size_t)ctaN*K;
  const int r0 = tid>>2, kq = tid&3;
  const int sts_off = r0*GSTRIDE + kq*4;

  // ldmatrix per-lane row/khalf selectors
  const int a_row = lane & 15, a_kh = (lane>>4)*8;
  const int b_row = lane & 7,  b_kh = ((lane>>3)&1)*8;

  unsigned smem_u32[2][4];
#pragma unroll
  for (int bf=0;bf<2;bf++)
#pragma unroll
    for (int q=0;q<4;q++) smem_u32[bf][q] = (unsigned)__cvta_generic_to_shared(sm[bf][q]);

  float4 ra0, ra1, rw0, rw1;
  // prologue: chunk 0
  ra0 = *(const float4*)(Abase + (size_t)r0*K + kq*4);
  ra1 = *(const float4*)(Abase + (size_t)(r0+64)*K + kq*4);
  rw0 = *(const float4*)(Wbase + (size_t)r0*K + kq*4);
  rw1 = *(const float4*)(Wbase + (size_t)(r0+64)*K + kq*4);
  cvt_store(&sm[0][0][sts_off],              &sm[0][1][sts_off],              ra0);
  cvt_store(&sm[0][0][sts_off+64*GSTRIDE],   &sm[0][1][sts_off+64*GSTRIDE],   ra1);
  cvt_store(&sm[0][2][sts_off],              &sm[0][3][sts_off],              rw0);
  cvt_store(&sm[0][2][sts_off+64*GSTRIDE],   &sm[0][3][sts_off+64*GSTRIDE],   rw1);
  __syncthreads();

  const int nchunk = K/16;
  for (int kc = 0; kc < nchunk; kc++){
    const int buf = kc & 1;
    if (kc+1 < nchunk){
      const float* ap = Abase + (kc+1)*16;
      const float* wp = Wbase + (kc+1)*16;
      ra0 = *(const float4*)(ap + (size_t)r0*K + kq*4);
      ra1 = *(const float4*)(ap + (size_t)(r0+64)*K + kq*4);
      rw0 = *(const float4*)(wp + (size_t)r0*K + kq*4);
      rw1 = *(const float4*)(wp + (size_t)(r0+64)*K + kq*4);
    }
    // B fragments (hi, lo) for 4 n-frags
    unsigned bh[4][2], bl[4][2];
#pragma unroll
    for (int nf=0;nf<4;nf++){
      unsigned off = (unsigned)((warpN + nf*8 + b_row)*GSTRIDE + b_kh)*2u;
      LDSM2(bh[nf], smem_u32[buf][2] + off);
      LDSM2(bl[nf], smem_u32[buf][3] + off);
    }
#pragma unroll
    for (int mf=0;mf<4;mf++){
      unsigned aoff = (unsigned)((warpM + mf*16 + a_row)*GSTRIDE + a_kh)*2u;
      unsigned ah[4], al[4];
      LDSM4(ah, smem_u32[buf][0] + aoff);
      LDSM4(al, smem_u32[buf][1] + aoff);
#pragma unroll
      for (int nf=0;nf<4;nf++){
        MMA16816(acc[mf][nf], ah, bh[nf]);
        MMA16816(acc[mf][nf], ah, bl[nf]);
        MMA16816(acc[mf][nf], al, bh[nf]);
      }
    }
    if (kc+1 < nchunk){
      const int nb = buf^1;
      cvt_store(&sm[nb][0][sts_off],            &sm[nb][1][sts_off],            ra0);
      cvt_store(&sm[nb][0][sts_off+64*GSTRIDE], &sm[nb][1][sts_off+64*GSTRIDE], ra1);
      cvt_store(&sm[nb][2][sts_off],            &sm[nb][3][sts_off],            rw0);
      cvt_store(&sm[nb][2][sts_off+64*GSTRIDE], &sm[nb][3][sts_off+64*GSTRIDE], rw1);
    }
    __syncthreads();
  }

  // epilogue
#pragma unroll
  for (int nf=0;nf<4;nf++){
    int col = ctaN + warpN + nf*8 + (lane&3)*2;
    float bb0 = b1[col]   + (b2 ? b2[col]   : 0.f);
    float bb1 = b1[col+1] + (b2 ? b2[col+1] : 0.f);
#pragma unroll
    for (int mf=0;mf<4;mf++){
      int row = ctaM + warpM + mf*16 + (lane>>2);
      float2 o0 = make_float2(acc[mf][nf][0]+bb0, acc[mf][nf][1]+bb1);
      float2 o1 = make_float2(acc[mf][nf][2]+bb0, acc[mf][nf][3]+bb1);
      *(float2*)(C + (size_t)row*N + col)     = o0;
      *(float2*)(C + (size_t)(row+8)*N + col) = o1;
    }
  }
}

// ---------- LSTM v2 (unchanged from round 3) --------------------------------
#define LS_SMEM (114688)
extern __shared__ float ls_smem[];

__launch_bounds__(256)
__global__ void lstm2_kernel(const float* __restrict__ W_hh)
{
  float* Ws  = ls_smem;
  float* hs0 = ls_smem + 8192;
  float* hs1 = ls_smem + 16384;
  float* red = ls_smem + 24576;

  const int t  = threadIdx.x;
  const int c0 = blockIdx.x*4;
  const int kw = t>>6;
  const int g  = (t>>4)&3;
  const int bq = t&15;
  const int fj = t>>6, fb = t&63;

  for (int id = t; id < 8192; id += 256){
    int row16 = id >> 9, k = id & 511;
    int gg = row16 >> 2, jj = row16 & 3;
    Ws[k*16 + row16] = W_hh[(size_t)(gg*DIM + c0 + jj)*DIM + k];
  }
  float cstate = 0.f;
  __syncthreads();

  for (int s = 0; s < SEQ; s++){
    const float* hbase = g_hT + (size_t)s*DIM*BATCH;
    const float* xgp = g_xg + ((size_t)s*BATCH + fb)*G4 + c0 + fj;
    float x0 = xgp[0], x1 = xgp[DIM], x2 = xgp[2*DIM], x3 = xgp[3*DIM];

#pragma unroll
    for (int i=0;i<8;i++){ int id = t + i*256; int row = id>>4, col = id&15;
      cp16(hs0 + row*64 + col*4, hbase + (size_t)row*64 + col*4); }
    CP_COMMIT();
#pragma unroll
    for (int i=0;i<8;i++){ int id = t + i*256; int row = id>>4, col = id&15;
      cp16(hs1 + row*64 + col*4, hbase + (size_t)(128+row)*64 + col*4); }
    CP_COMMIT();

    float acc[4][4];
#pragma unroll
    for (int a=0;a<4;a++)
#pragma unroll
      for (int b=0;b<4;b++) acc[a][b]=0.f;

#pragma unroll
    for (int sc = 0; sc < 4; sc++){
      CP_WAIT1();
      __syncthreads();
      const float* hc = (sc&1) ? hs1 : hs0;
      const float* wp = Ws + ((size_t)(sc*128 + kw*32))*16 + g*4;
      const float* hp = hc + (kw*32)*64 + bq*4;
#pragma unroll 8
      for (int k=0;k<32;k++){
        float4 w = *(const float4*)(wp + k*16);
        float4 h = *(const float4*)(hp + k*64);
        acc[0][0]+=w.x*h.x; acc[0][1]+=w.x*h.y; acc[0][2]+=w.x*h.z; acc[0][3]+=w.x*h.w;
        acc[1][0]+=w.y*h.x; acc[1][1]+=w.y*h.y; acc[1][2]+=w.y*h.z; acc[1][3]+=w.y*h.w;
        acc[2][0]+=w.z*h.x; acc[2][1]+=w.z*h.y; acc[2][2]+=w.z*h.z; acc[2][3]+=w.z*h.w;
        acc[3][0]+=w.w*h.x; acc[3][1]+=w.w*h.y; acc[3][2]+=w.w*h.z; acc[3][3]+=w.w*h.w;
      }
      __syncthreads();
      if (sc < 2){
        float* dst = (sc&1) ? hs1 : hs0;
#pragma unroll
        for (int i=0;i<8;i++){ int id = t + i*256; int row = id>>4, col = id&15;
          cp16(dst + row*64 + col*4, hbase + (size_t)((sc+2)*128+row)*64 + col*4); }
      }
      CP_COMMIT();
    }

#pragma unroll
    for (int a=0;a<4;a++)
      *(float4*)&red[(size_t)(kw*16 + g*4 + a)*64 + bq*4] =
          make_float4(acc[a][0],acc[a][1],acc[a][2],acc[a][3]);
    __syncthreads();

    float gi = x0, gf = x1, gg2 = x2, go = x3;
#pragma unroll
    for (int k2=0;k2<4;k2++){
      gi  += red[(k2*16 +  0 + fj)*64 + fb];
      gf  += red[(k2*16 +  4 + fj)*64 + fb];
      gg2 += red[(k2*16 +  8 + fj)*64 + fb];
      go  += red[(k2*16 + 12 + fj)*64 + fb];
    }
    cstate = sigf(gf)*cstate + sigf(gi)*tanhf(gg2);
    g_hT[((size_t)(s+1)*DIM + (c0+fj))*BATCH + fb] = sigf(go)*tanhf(cstate);

    __syncthreads();
    if (t==0){
      __threadfence();
      atomicAdd(&g_bar, 1u);
      unsigned target = (unsigned)(s+1)*128u;
      while (*(volatile unsigned*)&g_bar < target) { }
    }
    __syncthreads();
  }
}

// actions[s][b][a] = h[s] @ W_act.T + b_act  (N=72)
__launch_bounds__(256)
__global__ void actions_kernel(const float* __restrict__ W_act, const float* __restrict__ b_act)
{
  __shared__ float hs[64*64];
  __shared__ float ws[NACT*64];
  const int s = blockIdx.x, t = threadIdx.x;
  const int b = t&63, ag = t>>6;
  const float* hT = g_hT + (size_t)(s+1)*DIM*BATCH;
  float acc[18];
#pragma unroll
  for (int i=0;i<18;i++) acc[i]=0.f;

  for (int j0=0;j0<DIM;j0+=64){
#pragma unroll
    for (int i=0;i<4;i++){
      int id = t + i*256;
      ((float4*)hs)[id] = ((const float4*)(hT + (size_t)j0*BATCH))[id];
    }
    for (int i=t;i<NACT*16;i+=256){
      int a = i>>4, jj = i&15;
      *(float4*)&ws[a*64 + jj*4] = *(const float4*)(W_act + (size_t)a*DIM + j0 + jj*4);
    }
    __syncthreads();
#pragma unroll 8
    for (int j=0;j<64;j++){
      float hv = hs[j*64 + b];
#pragma unroll
      for (int ii=0;ii<18;ii++) acc[ii] += hv * ws[(ag*18+ii)*64 + j];
    }
    __syncthreads();
  }
#pragma unroll
  for (int ii=0;ii<18;ii++){
    int a = ag*18+ii;
    g_act[((size_t)s*BATCH + b)*NACT + a] = acc[ii] + b_act[a];
  }
}

// NTM scan: 1 CTA per (batch,tape); thread c owns tape[:,c] in regs
__launch_bounds__(64)
__global__ void tape_kernel(float* __restrict__ out)
{
  __shared__ float wpos[TL], rpos[TL], rpr[TL];
  const int bb = blockIdx.x>>3, tp = blockIdx.x&7, c = threadIdx.x;
  float tape[TL];
#pragma unroll
  for (int l=0;l<TL;l++) tape[l]=0.f;
  wpos[c] = (c==0)?1.f:0.f;
  rpos[c] = (c==0)?1.f:0.f;
  __syncthreads();

  for (int s=0;s<SEQ;s++){
    const float* ap = g_act + ((size_t)s*BATCH + bb)*NACT + tp*9;
    float r0=ap[0], r1=ap[1], r2=ap[2];
    float w0=ap[3], w1=ap[4], w2=ap[5];
    float rw0=sigf(ap[6]), rw1=sigf(ap[7]), rw2=sigf(ap[8]);

    float mr = fmaxf(r0,fmaxf(r1,r2));
    float e0=__expf(r0-mr), e1=__expf(r1-mr), e2=__expf(r2-mr);
    float ir = 1.f/(e0+e1+e2);
    float rd0=e0*ir, rd1=e1*ir, rd2=e2*ir;
    float mw = fmaxf(w0,fmaxf(w1,w2));
    float f0=__expf(w0-mw), f1=__expf(w1-mw), f2=__expf(w2-mw);
    float iw = 1.f/(f0+f1+f2);
    float wd0=f0*iw, wd1=f1*iw, wd2=f2*iw;

    float v = g_val[((size_t)s*BATCH + bb)*DIM + tp*HD + c];

    float oldv = 0.f;
#pragma unroll
    for (int l=0;l<TL;l++) oldv += tape[l]*wpos[l];

    float nw = wpos[(c+1)&63]*wd0 + wpos[c]*wd1 + wpos[(c+63)&63]*wd2;
    float nr = rpos[(c+1)&63]*rd0 + rpos[c]*rd1 + rpos[(c+63)&63]*rd2;
    rpr[c] = rpos[c]*rw0;
    __syncthreads();

    float upd = v*rw1 - oldv*rw2;
    float ro = 0.f;
#pragma unroll
    for (int l=0;l<TL;l++){
      tape[l] += wpos[l]*upd;
      ro += tape[l]*rpr[l];
    }
    __syncthreads();
    wpos[c]=nw; rpos[c]=nr;
    g_ro[((size_t)s*BATCH + bb)*DIM + tp*HD + c] = ro;
    __syncthreads();
  }
#pragma unroll
  for (int l=0;l<TL;l++)
    out[(size_t)SEQ*BATCH*DIM + ((size_t)l*BATCH + bb)*DIM + tp*HD + c] = tape[l];
}

extern "C" void kernel_launch(void* const* d_in, const int* in_sizes, int n_in,
                              void* d_out, int out_size)
{
  const float* inputs = (const float*)d_in[0];
  const float* W_ih   = (const float*)d_in[1];
  const float* W_hh   = (const float*)d_in[2];
  const float* b_ih   = (const float*)d_in[3];
  const float* b_hh   = (const float*)d_in[4];
  const float* W_act  = (const float*)d_in[5];
  const float* b_act  = (const float*)d_in[6];
  const float* W_val  = (const float*)d_in[7];
  const float* b_val  = (const float*)d_in[8];
  const float* W_out  = (const float*)d_in[9];
  const float* b_out  = (const float*)d_in[10];
  float* out = (float*)d_out;

  float *xg_p, *val_p, *ro_p;
  cudaGetSymbolAddress((void**)&xg_p,  g_xg);
  cudaGetSymbolAddress((void**)&val_p, g_val);
  cudaGetSymbolAddress((void**)&ro_p,  g_ro);

  cudaFuncSetAttribute(lstm2_kernel, cudaFuncAttributeMaxDynamicSharedMemorySize, LS_SMEM);

  init_kernel<<<128,256>>>();
  tgemm_bias<<<dim3(16,256),256>>>(inputs, W_ih, b_ih, b_hh, xg_p, G4, DIM);
  tgemm_bias<<<dim3(4,256),256>>>(inputs, W_val, b_val, nullptr, val_p, DIM, DIM);
  lstm2_kernel<<<128,256,LS_SMEM>>>(W_hh);
  actions_kernel<<<SEQ,256>>>(W_act, b_act);
  tape_kernel<<<512,64>>>(out);
  tgemm_bias<<<dim3(4,256),256>>>(ro_p, W_out, b_out, nullptr, out, DIM, DIM);
}

// round 5
// speedup vs baseline: 3.9155x; 1.2449x over previous
#include <cuda_runtime.h>
#include <cuda_bf16.h>
#include <math.h>

#define SEQ   512
#define BATCH 64
#define DIM   512
#define G4    2048
#define NT    8
#define HD    64
#define TL    64
#define NACT  72
#define MROWS (SEQ*BATCH)

__device__ float g_xg [(size_t)MROWS*G4];
__device__ float g_val[(size_t)MROWS*DIM];
__device__ float g_hT [(size_t)(SEQ+1)*DIM*BATCH];
__device__ float g_act[(size_t)MROWS*NACT];
__device__ float g_ro [(size_t)MROWS*DIM];
__device__ __nv_bfloat16 g_hbh[2][BATCH*DIM];   // h hi plane, [buf][b][k]
__device__ __nv_bfloat16 g_hbl[2][BATCH*DIM];   // h lo plane
__device__ unsigned g_bar;

__device__ __forceinline__ float sigf(float x){ return 1.f/(1.f+__expf(-x)); }

__device__ __forceinline__ void cp16(void* dst_smem, const void* src){
  unsigned d = (unsigned)__cvta_generic_to_shared(dst_smem);
  asm volatile("cp.async.ca.shared.global [%0], [%1], 16;\n" :: "r"(d), "l"(src));
}
#define CP_COMMIT() asm volatile("cp.async.commit_group;\n" ::: "memory")
#define CP_WAIT0()  asm volatile("cp.async.wait_group 0;\n" ::: "memory")

__global__ void init_kernel(){
  unsigned i = blockIdx.x*256u + threadIdx.x;
  if (i==0) g_bar = 0u;
  if (i < DIM*BATCH){
    g_hT[i] = 0.f;
    g_hbh[0][i] = __float2bfloat16(0.f);
    g_hbl[0][i] = __float2bfloat16(0.f);
  }
}

// ================= bf16-split tensor GEMM (validated round 4) ===============
#define GSTRIDE 24

__device__ __forceinline__ void cvt_store(__nv_bfloat16* Hp, __nv_bfloat16* Lp, float4 v){
  __nv_bfloat16 h0=__float2bfloat16(v.x), h1=__float2bfloat16(v.y);
  __nv_bfloat16 h2=__float2bfloat16(v.z), h3=__float2bfloat16(v.w);
  __nv_bfloat16 l0=__float2bfloat16(v.x-__bfloat162float(h0));
  __nv_bfloat16 l1=__float2bfloat16(v.y-__bfloat162float(h1));
  __nv_bfloat16 l2=__float2bfloat16(v.z-__bfloat162float(h2));
  __nv_bfloat16 l3=__float2bfloat16(v.w-__bfloat162float(h3));
  ((__nv_bfloat162*)Hp)[0] = __nv_bfloat162(h0,h1);
  ((__nv_bfloat162*)Hp)[1] = __nv_bfloat162(h2,h3);
  ((__nv_bfloat162*)Lp)[0] = __nv_bfloat162(l0,l1);
  ((__nv_bfloat162*)Lp)[1] = __nv_bfloat162(l2,l3);
}

#define MMA16816(C, A, B) \
  asm volatile("mma.sync.aligned.m16n8k16.row.col.f32.bf16.bf16.f32 " \
    "{%0,%1,%2,%3}, {%4,%5,%6,%7}, {%8,%9}, {%0,%1,%2,%3};" \
    : "+f"((C)[0]),"+f"((C)[1]),"+f"((C)[2]),"+f"((C)[3]) \
    : "r"((A)[0]),"r"((A)[1]),"r"((A)[2]),"r"((A)[3]), "r"((B)[0]),"r"((B)[1]))

#define LDSM4(R, addr) \
  asm volatile("ldmatrix.sync.aligned.m8n8.x4.shared.b16 {%0,%1,%2,%3}, [%4];" \
    : "=r"((R)[0]),"=r"((R)[1]),"=r"((R)[2]),"=r"((R)[3]) : "r"(addr))

#define LDSM2(R, addr) \
  asm volatile("ldmatrix.sync.aligned.m8n8.x2.shared.b16 {%0,%1}, [%2];" \
    : "=r"((R)[0]),"=r"((R)[1]) : "r"(addr))

__launch_bounds__(256)
__global__ void tgemm_bias(const float* __restrict__ A, const float* __restrict__ W,
                           const float* __restrict__ b1, const float* __restrict__ b2,
                           float* __restrict__ C, int N, int K)
{
  __shared__ __nv_bfloat16 sm[2][4][128*GSTRIDE];
  const int tid = threadIdx.x;
  const int lane = tid & 31, warp = tid >> 5;
  const int warpM = (warp>>2)*64, warpN = (warp&3)*32;
  const int ctaM = blockIdx.y*128, ctaN = blockIdx.x*128;

  float acc[4][4][4];
#pragma unroll
  for (int mf=0;mf<4;mf++)
#pragma unroll
    for (int nf=0;nf<4;nf++)
#pragma unroll
      for (int i=0;i<4;i++) acc[mf][nf][i]=0.f;

  const float* Abase = A + (size_t)ctaM*K;
  const float* Wbase = W + (size_t)ctaN*K;
  const int r0 = tid>>2, kq = tid&3;
  const int sts_off = r0*GSTRIDE + kq*4;
  const int a_row = lane & 15, a_kh = (lane>>4)*8;
  const int b_row = lane & 7,  b_kh = ((lane>>3)&1)*8;

  unsigned smem_u32[2][4];
#pragma unroll
  for (int bf=0;bf<2;bf++)
#pragma unroll
    for (int q=0;q<4;q++) smem_u32[bf][q] = (unsigned)__cvta_generic_to_shared(sm[bf][q]);

  float4 ra0, ra1, rw0, rw1;
  ra0 = *(const float4*)(Abase + (size_t)r0*K + kq*4);
  ra1 = *(const float4*)(Abase + (size_t)(r0+64)*K + kq*4);
  rw0 = *(const float4*)(Wbase + (size_t)r0*K + kq*4);
  rw1 = *(const float4*)(Wbase + (size_t)(r0+64)*K + kq*4);
  cvt_store(&sm[0][0][sts_off],              &sm[0][1][sts_off],              ra0);
  cvt_store(&sm[0][0][sts_off+64*GSTRIDE],   &sm[0][1][sts_off+64*GSTRIDE],   ra1);
  cvt_store(&sm[0][2][sts_off],              &sm[0][3][sts_off],              rw0);
  cvt_store(&sm[0][2][sts_off+64*GSTRIDE],   &sm[0][3][sts_off+64*GSTRIDE],   rw1);
  __syncthreads();

  const int nchunk = K/16;
  for (int kc = 0; kc < nchunk; kc++){
    const int buf = kc & 1;
    if (kc+1 < nchunk){
      const float* ap = Abase + (kc+1)*16;
      const float* wp = Wbase + (kc+1)*16;
      ra0 = *(const float4*)(ap + (size_t)r0*K + kq*4);
      ra1 = *(const float4*)(ap + (size_t)(r0+64)*K + kq*4);
      rw0 = *(const float4*)(wp + (size_t)r0*K + kq*4);
      rw1 = *(const float4*)(wp + (size_t)(r0+64)*K + kq*4);
    }
    unsigned bh[4][2], bl[4][2];
#pragma unroll
    for (int nf=0;nf<4;nf++){
      unsigned off = (unsigned)((warpN + nf*8 + b_row)*GSTRIDE + b_kh)*2u;
      LDSM2(bh[nf], smem_u32[buf][2] + off);
      LDSM2(bl[nf], smem_u32[buf][3] + off);
    }
#pragma unroll
    for (int mf=0;mf<4;mf++){
      unsigned aoff = (unsigned)((warpM + mf*16 + a_row)*GSTRIDE + a_kh)*2u;
      unsigned ah[4], al[4];
      LDSM4(ah, smem_u32[buf][0] + aoff);
      LDSM4(al, smem_u32[buf][1] + aoff);
#pragma unroll
      for (int nf=0;nf<4;nf++){
        MMA16816(acc[mf][nf], ah, bh[nf]);
        MMA16816(acc[mf][nf], ah, bl[nf]);
        MMA16816(acc[mf][nf], al, bh[nf]);
      }
    }
    if (kc+1 < nchunk){
      const int nb = buf^1;
      cvt_store(&sm[nb][0][sts_off],            &sm[nb][1][sts_off],            ra0);
      cvt_store(&sm[nb][0][sts_off+64*GSTRIDE], &sm[nb][1][sts_off+64*GSTRIDE], ra1);
      cvt_store(&sm[nb][2][sts_off],            &sm[nb][3][sts_off],            rw0);
      cvt_store(&sm[nb][2][sts_off+64*GSTRIDE], &sm[nb][3][sts_off+64*GSTRIDE], rw1);
    }
    __syncthreads();
  }

#pragma unroll
  for (int nf=0;nf<4;nf++){
    int col = ctaN + warpN + nf*8 + (lane&3)*2;
    float bb0 = b1[col]   + (b2 ? b2[col]   : 0.f);
    float bb1 = b1[col+1] + (b2 ? b2[col+1] : 0.f);
#pragma unroll
    for (int mf=0;mf<4;mf++){
      int row = ctaM + warpM + mf*16 + (lane>>2);
      *(float2*)(C + (size_t)row*N + col)     = make_float2(acc[mf][nf][0]+bb0, acc[mf][nf][1]+bb1);
      *(float2*)(C + (size_t)(row+8)*N + col) = make_float2(acc[mf][nf][2]+bb0, acc[mf][nf][3]+bb1);
    }
  }
}

// ---------- LSTM v3: tensor-core recurrence ----------------------------------
// 128 CTAs x 256 thr. CTA = 16 gate rows (4 hidden cols) x 64 batches x K=512.
// 8 warps: mw=w&3 (16-batch m-tile), kh=w>>2 (256-k split). Warp loads its own
// A tile (cp.async), ldmatrix+HMMA 3-pass hi/lo, split-K reduce in SMEM.
// SMEM (bf16): Whi[16*520] Wlo[16*520] Hhi[64*520] Hlo[64*520], then red fp32.
#define HST 520
#define WHI 0
#define WLO (16*HST)
#define HHI (32*HST)
#define HLO (96*HST)
#define REDOFF 41600                    // float index: 160*520*2B / 4
#define LS3_SMEM (160*HST*2 + 2*16*68*4)   // 166400 + 8704 = 175104

extern __shared__ float ls_smem[];

__launch_bounds__(256)
__global__ void lstm3_kernel(const float* __restrict__ W_hh)
{
  __nv_bfloat16* sb = (__nv_bfloat16*)ls_smem;
  float* red = ls_smem + REDOFF;

  const int t = threadIdx.x, lane = t&31, w = t>>5;
  const int c0 = blockIdx.x*4;
  const int mw = w&3, kh = w>>2;
  const int fj = t>>6, fb = t&63;
  const int a_row = lane & 15, a_kh = (lane>>4)*8;
  const int b_row = lane & 7,  b_kh = ((lane>>3)&1)*8;

  // resident W (bf16 hi/lo), loaded once
  for (int id=t; id<16*512; id+=256){
    int row16 = id>>9, k = id&511;
    int gg = row16>>2, jj = row16&3;
    float v = W_hh[(size_t)(gg*DIM + c0 + jj)*DIM + k];
    __nv_bfloat16 hv = __float2bfloat16(v);
    sb[WHI + row16*HST + k] = hv;
    sb[WLO + row16*HST + k] = __float2bfloat16(v - __bfloat162float(hv));
  }
  float cstate = 0.f;
  __syncthreads();

  const unsigned sb_u = (unsigned)__cvta_generic_to_shared(sb);

  for (int s=0; s<SEQ; s++){
    // xg prefetch (final role; consumed after reduce)
    const float* xgp = g_xg + ((size_t)s*BATCH + fb)*G4 + c0 + fj;
    float x0 = xgp[0], x1 = xgp[DIM], x2 = xgp[2*DIM], x3 = xgp[3*DIM];

    // warp-private A tile: 16 batches x 256 k, hi+lo
    {
      const __nv_bfloat16* srcH = g_hbh[s&1];
      const __nv_bfloat16* srcL = g_hbl[s&1];
#pragma unroll
      for (int i=0;i<16;i++){
        int idx = lane + i*32;            // 0..511
        int row = idx>>5, ch = idx&31;
        int soff = (mw*16+row)*HST + kh*256 + ch*8;
        int goff = (mw*16+row)*512 + kh*256 + ch*8;
        cp16(sb + HHI + soff, srcH + goff);
        cp16(sb + HLO + soff, srcL + goff);
      }
      CP_COMMIT();
      CP_WAIT0();
      __syncwarp();
    }

    float acc[2][4];
#pragma unroll
    for (int nf=0;nf<2;nf++)
#pragma unroll
      for (int i=0;i<4;i++) acc[nf][i]=0.f;

#pragma unroll 4
    for (int ks=0; ks<16; ks++){
      const int kbase = kh*256 + ks*16;
      unsigned ah[4], al[4];
      unsigned aoff = (unsigned)((HHI) + (mw*16 + a_row)*HST + kbase + a_kh)*2u;
      unsigned loff = (unsigned)((HLO) + (mw*16 + a_row)*HST + kbase + a_kh)*2u;
      LDSM4(ah, sb_u + aoff);
      LDSM4(al, sb_u + loff);
#pragma unroll
      for (int nf=0;nf<2;nf++){
        unsigned bh[2], bl[2];
        unsigned bo = (unsigned)((nf*8 + b_row)*HST + kbase + b_kh)*2u;
        LDSM2(bh, sb_u + (unsigned)(WHI*2) + bo);
        LDSM2(bl, sb_u + (unsigned)(WLO*2) + bo);
        MMA16816(acc[nf], ah, bh);
        MMA16816(acc[nf], ah, bl);
        MMA16816(acc[nf], al, bh);
      }
    }

    // split-K reduce via SMEM: red[(kh*16+n)*68 + b]
#pragma unroll
    for (int nf=0;nf<2;nf++){
      int n0 = nf*8 + (lane&3)*2;
      int b0 = mw*16 + (lane>>2);
      red[(kh*16 + n0  )*68 + b0  ] = acc[nf][0];
      red[(kh*16 + n0+1)*68 + b0  ] = acc[nf][1];
      red[(kh*16 + n0  )*68 + b0+8] = acc[nf][2];
      red[(kh*16 + n0+1)*68 + b0+8] = acc[nf][3];
    }
    __syncthreads();

    {
      float gi=x0, gf=x1, gg2=x2, go=x3;
#pragma unroll
      for (int k2=0;k2<2;k2++){
        gi  += red[(k2*16 +  0 + fj)*68 + fb];
        gf  += red[(k2*16 +  4 + fj)*68 + fb];
        gg2 += red[(k2*16 +  8 + fj)*68 + fb];
        go  += red[(k2*16 + 12 + fj)*68 + fb];
      }
      cstate = sigf(gf)*cstate + sigf(gi)*tanhf(gg2);
      float hv = sigf(go)*tanhf(cstate);
      g_hT[((size_t)(s+1)*DIM + (c0+fj))*BATCH + fb] = hv;
      __nv_bfloat16 hh = __float2bfloat16(hv);
      g_hbh[(s+1)&1][fb*512 + c0 + fj] = hh;
      g_hbl[(s+1)&1][fb*512 + c0 + fj] = __float2bfloat16(hv - __bfloat162float(hh));
    }
    __syncthreads();
    if (t==0){
      __threadfence();
      atomicAdd(&g_bar, 1u);
      unsigned target = (unsigned)(s+1)*128u;
      while (*(volatile unsigned*)&g_bar < target) { }
    }
    __syncthreads();
  }
}

// actions[s][b][a] = h[s] @ W_act.T + b_act  (N=72)
__launch_bounds__(256)
__global__ void actions_kernel(const float* __restrict__ W_act, const float* __restrict__ b_act)
{
  __shared__ float hs[64*64];
  __shared__ float ws[NACT*64];
  const int s = blockIdx.x, t = threadIdx.x;
  const int b = t&63, ag = t>>6;
  const float* hT = g_hT + (size_t)(s+1)*DIM*BATCH;
  float acc[18];
#pragma unroll
  for (int i=0;i<18;i++) acc[i]=0.f;

  for (int j0=0;j0<DIM;j0+=64){
#pragma unroll
    for (int i=0;i<4;i++){
      int id = t + i*256;
      ((float4*)hs)[id] = ((const float4*)(hT + (size_t)j0*BATCH))[id];
    }
    for (int i=t;i<NACT*16;i+=256){
      int a = i>>4, jj = i&15;
      *(float4*)&ws[a*64 + jj*4] = *(const float4*)(W_act + (size_t)a*DIM + j0 + jj*4);
    }
    __syncthreads();
#pragma unroll 8
    for (int j=0;j<64;j++){
      float hv = hs[j*64 + b];
#pragma unroll
      for (int ii=0;ii<18;ii++) acc[ii] += hv * ws[(ag*18+ii)*64 + j];
    }
    __syncthreads();
  }
#pragma unroll
  for (int ii=0;ii<18;ii++){
    int a = ag*18+ii;
    g_act[((size_t)s*BATCH + b)*NACT + a] = acc[ii] + b_act[a];
  }
}

// NTM scan: 1 CTA per (batch,tape); thread c owns tape[:,c] in regs
__launch_bounds__(64)
__global__ void tape_kernel(float* __restrict__ out)
{
  __shared__ float wpos[TL], rpos[TL], rpr[TL];
  const int bb = blockIdx.x>>3, tp = blockIdx.x&7, c = threadIdx.x;
  float tape[TL];
#pragma unroll
  for (int l=0;l<TL;l++) tape[l]=0.f;
  wpos[c] = (c==0)?1.f:0.f;
  rpos[c] = (c==0)?1.f:0.f;
  __syncthreads();

  for (int s=0;s<SEQ;s++){
    const float* ap = g_act + ((size_t)s*BATCH + bb)*NACT + tp*9;
    float r0=ap[0], r1=ap[1], r2=ap[2];
    float w0=ap[3], w1=ap[4], w2=ap[5];
    float rw0=sigf(ap[6]), rw1=sigf(ap[7]), rw2=sigf(ap[8]);

    float mr = fmaxf(r0,fmaxf(r1,r2));
    float e0=__expf(r0-mr), e1=__expf(r1-mr), e2=__expf(r2-mr);
    float ir = 1.f/(e0+e1+e2);
    float rd0=e0*ir, rd1=e1*ir, rd2=e2*ir;
    float mw = fmaxf(w0,fmaxf(w1,w2));
    float f0=__expf(w0-mw), f1=__expf(w1-mw), f2=__expf(w2-mw);
    float iw = 1.f/(f0+f1+f2);
    float wd0=f0*iw, wd1=f1*iw, wd2=f2*iw;

    float v = g_val[((size_t)s*BATCH + bb)*DIM + tp*HD + c];

    float oldv = 0.f;
#pragma unroll
    for (int l=0;l<TL;l++) oldv += tape[l]*wpos[l];

    float nw = wpos[(c+1)&63]*wd0 + wpos[c]*wd1 + wpos[(c+63)&63]*wd2;
    float nr = rpos[(c+1)&63]*rd0 + rpos[c]*rd1 + rpos[(c+63)&63]*rd2;
    rpr[c] = rpos[c]*rw0;
    __syncthreads();

    float upd = v*rw1 - oldv*rw2;
    float ro = 0.f;
#pragma unroll
    for (int l=0;l<TL;l++){
      tape[l] += wpos[l]*upd;
      ro += tape[l]*rpr[l];
    }
    __syncthreads();
    wpos[c]=nw; rpos[c]=nr;
    g_ro[((size_t)s*BATCH + bb)*DIM + tp*HD + c] = ro;
    __syncthreads();
  }
#pragma unroll
  for (int l=0;l<TL;l++)
    out[(size_t)SEQ*BATCH*DIM + ((size_t)l*BATCH + bb)*DIM + tp*HD + c] = tape[l];
}

extern "C" void kernel_launch(void* const* d_in, const int* in_sizes, int n_in,
                              void* d_out, int out_size)
{
  const float* inputs = (const float*)d_in[0];
  const float* W_ih   = (const float*)d_in[1];
  const float* W_hh   = (const float*)d_in[2];
  const float* b_ih   = (const float*)d_in[3];
  const float* b_hh   = (const float*)d_in[4];
  const float* W_act  = (const float*)d_in[5];
  const float* b_act  = (const float*)d_in[6];
  const float* W_val  = (const float*)d_in[7];
  const float* b_val  = (const float*)d_in[8];
  const float* W_out  = (const float*)d_in[9];
  const float* b_out  = (const float*)d_in[10];
  float* out = (float*)d_out;

  float *xg_p, *val_p, *ro_p;
  cudaGetSymbolAddress((void**)&xg_p,  g_xg);
  cudaGetSymbolAddress((void**)&val_p, g_val);
  cudaGetSymbolAddress((void**)&ro_p,  g_ro);

  cudaFuncSetAttribute(lstm3_kernel, cudaFuncAttributeMaxDynamicSharedMemorySize, LS3_SMEM);

  init_kernel<<<128,256>>>();
  tgemm_bias<<<dim3(16,256),256>>>(inputs, W_ih, b_ih, b_hh, xg_p, G4, DIM);
  tgemm_bias<<<dim3(4,256),256>>>(inputs, W_val, b_val, nullptr, val_p, DIM, DIM);
  lstm3_kernel<<<128,256,LS3_SMEM>>>(W_hh);
  actions_kernel<<<SEQ,256>>>(W_act, b_act);
  tape_kernel<<<512,64>>>(out);
  tgemm_bias<<<dim3(4,256),256>>>(ro_p, W_out, b_out, nullptr, out, DIM, DIM);
}